// round 13
// baseline (speedup 1.0000x reference)
#include <cuda_runtime.h>

#define BB 4096
#define TT 1024
#define NN 16
#define NPT 2   // packed pairs per thread: 4 threads/row * 2 pairs * 2 = 16 filters
#define TQ (TT / 4)

// Quad-packed transposed currents: g_cur4[tq][b] = {cur[4tq..4tq+3]} for row b.
__device__ float4 g_cur4[(TQ + 4) * BB];

typedef unsigned long long u64;

__device__ __forceinline__ u64 pk2(float x, float y) {
    u64 r; asm("mov.b64 %0, {%1, %2};" : "=l"(r) : "f"(x), "f"(y)); return r;
}
__device__ __forceinline__ void upk2(u64 a, float& x, float& y) {
    asm("mov.b64 {%0, %1}, %2;" : "=f"(x), "=f"(y) : "l"(a));
}
__device__ __forceinline__ u64 fma2_(u64 a, u64 b, u64 c) {
    u64 d; asm("fma.rn.f32x2 %0, %1, %2, %3;" : "=l"(d) : "l"(a), "l"(b), "l"(c)); return d;
}
__device__ __forceinline__ u64 mul2_(u64 a, u64 b) {
    u64 d; asm("mul.rn.f32x2 %0, %1, %2;" : "=l"(d) : "l"(a), "l"(b)); return d;
}
__device__ __forceinline__ float ex2_a(float x) {
    float y; asm("ex2.approx.f32 %0, %1;" : "=f"(y) : "f"(x)); return y;
}
__device__ __forceinline__ float rcp_a(float x) {
    float y; asm("rcp.approx.f32 %0, %1;" : "=f"(y) : "f"(x)); return y;
}

// ---------------------------------------------------------------------------
// Pass 1: transpose + quad-pack currents (B,T) -> g_cur4 (T/4, B) float4.
// ---------------------------------------------------------------------------
__global__ void transpose_kernel(const float* __restrict__ cur) {
    __shared__ float tile[32][33];
    const int tx = threadIdx.x, ty = threadIdx.y;
    const int t0 = blockIdx.x * 32, b0 = blockIdx.y * 32;
#pragma unroll
    for (int i = 0; i < 32; i += 8)
        tile[ty + i][tx] = cur[(size_t)(b0 + ty + i) * TT + (t0 + tx)];
    __syncthreads();
    float4 val;
    val.x = tile[tx][4 * ty + 0];
    val.y = tile[tx][4 * ty + 1];
    val.z = tile[tx][4 * ty + 2];
    val.w = tile[tx][4 * ty + 3];
    g_cur4[(size_t)((t0 >> 2) + ty) * BB + (b0 + tx)] = val;
}

// ---------------------------------------------------------------------------
// Pass 2: EXACTLY R9 (best: 53.3us) except the nonlinearity.
//
// ABLATION: MUFU.TANH is the only critical-chain op with UNDOCUMENTED
// latency (absent from the measured MUFU table: RCP/RSQ/SQRT/SIN/COS/EX2/LG2
// = 16cyc). Replace with documented MUFUs:
//     th = tanh(relu(p)) = 2/(1 + e^{-2*relu(p)}) - 1
//                        = fma(2, rcp(1 + ex2(pn)), -1),  pn = min(-L*p, 0)
// where L = 2*log2(e) and the -L factor is folded into the squared poly
// coefficients (qk' = -L*qk, exact preprocessing; relu(p) -> min(-Lp, 0)).
// Chain: poly(20) + EX2(16) + FADD(4) + RCP(16) + FFMA(4) = 60 cyc of
// KNOWN-latency ops, zero extra multiplies.
// ---------------------------------------------------------------------------
__global__ void __launch_bounds__(128, 1) gfr_kernel(
    const float* __restrict__ a, const float* __restrict__ b,
    const float* __restrict__ pc, const float* __restrict__ gb,
    const float* __restrict__ ds, const float* __restrict__ mc,
    const float* __restrict__ mfr, float* __restrict__ out)
{
    const int tid = threadIdx.x;
    const int sub = tid & 3;
    const int row = blockIdx.x * 32 + (tid >> 2);
    const int f0  = sub * 4;

    const float MFR = mfr[0];
    const float invmc = 1.f / mc[0];
    const float csN = invmc * (1.f / (float)NN);

    u64 av[NPT], bv[NPT], dv[NPT], d3v[NPT], v[NPT];
#pragma unroll
    for (int i = 0; i < NPT; i++) {
        const float dA = 1.f - ds[f0 + 2 * i], dB = 1.f - ds[f0 + 2 * i + 1];
        av[i]  = pk2(csN * a[f0 + 2 * i], csN * a[f0 + 2 * i + 1]);
        bv[i]  = pk2(csN * 1000.f * MFR * b[f0 + 2 * i],
                     csN * 1000.f * MFR * b[f0 + 2 * i + 1]);
        dv[i]  = pk2(dA, dB);
        d3v[i] = pk2(dA * dA * dA, dB * dB * dB);
        v[i] = 0ull;
    }
    float suma = 0.f, sumb = 0.f, a1c = 0.f, b1c = 0.f, a2c = 0.f, b2c = 0.f;
#pragma unroll
    for (int n = 0; n < NN; n++) {
        const float dn = 1.f - ds[n];
        const float An = csN * a[n];
        const float Bn = csN * 1000.f * MFR * b[n];
        suma += a[n]; sumb += b[n];
        a1c += dn * An;        b1c += dn * Bn;
        a2c += dn * dn * An;   b2c += dn * dn * Bn;
    }
    const float ca = suma * csN;
    const float cb = 1000.f * MFR * sumb * csN;
    const float c0 = -gb[0] * invmc;
    // squared poly coefficients, pre-scaled by -L (L = 2*log2 e) so the
    // poly directly yields pn = -L*p; then th = fma(2, rcp(1+ex2(min(pn,0))), -1)
    const float Lm = -2.f * 1.4426950408889634f;
    const float q0 = Lm * pc[0] * pc[0], q1 = Lm * pc[1] * pc[1],
                q2 = Lm * pc[2] * pc[2], q3 = Lm * pc[3] * pc[3],
                q4 = Lm * pc[4] * pc[4];

    const float4* cp4 = g_cur4 + row;
    float* op = out + row + (size_t)sub * BB;
    float th = 0.f, M1 = 0.f, M2 = 0.f;

    float4 q0buf = __ldg(cp4);
    float4 q1buf = __ldg(cp4 + BB);

#define STEP(CUR, J)                                                        \
    {                                                                       \
        const float cur_ = (CUR);                                           \
        const float pre_ = fmaf(cur_, ca, c0);                              \
        /* ---- th critical path (uses carried M1 = M_1[t-1]) ---- */       \
        const float x_ = fmaf(th, cb, M1 + pre_);                           \
        const float x2_ = x_ * x_;                                          \
        const float u01_ = fmaf(q1, x_, q0);                                \
        const float u34_ = fmaf(q4, x_, q3);                                \
        const float w1s_ = fmaf(q2, x2_, u01_);                             \
        const float x3_ = x_ * x2_;                                         \
        float pn_ = fmaf(u34_, x3_, w1s_);  /* = -L * p */                  \
        pn_ = fminf(pn_, 0.f);              /* relu(p) -> min(-Lp, 0) */    \
        const float e_  = ex2_a(pn_);       /* e^{-2 relu(p)} in (0,1] */   \
        const float r_  = rcp_a(1.f + e_);                                  \
        const float thn_ = fmaf(2.f, r_, -1.f);                             \
        /* ---- reduction M_3[t-1] from state V[t-1] (big slack) ---- */    \
        u64 s_ = fma2_(d3v[1], v[1], mul2_(d3v[0], v[0]));                  \
        float sx_, sy_; upk2(s_, sx_, sy_);                                 \
        const float Wp_ = sx_ + sy_;                                        \
        const float r1_ = Wp_ + __shfl_xor_sync(0xFFFFFFFFu, Wp_, 1);       \
        const float R3_ = r1_ + __shfl_xor_sync(0xFFFFFFFFu, r1_, 2);       \
        /* ---- moment pipeline ---- */                                     \
        const float M1n_ = M2 + fmaf(th, b1c, cur_ * a1c);                  \
        const float M2n_ = R3_ + fmaf(th, b2c, cur_ * a2c);                 \
        /* ---- state update with OLD th ---- */                            \
        const u64 cur2_ = pk2(cur_, cur_);                                  \
        const u64 th2_  = pk2(th, th);                                      \
        v[0] = fma2_(dv[0], v[0], fma2_(th2_, bv[0], mul2_(cur2_, av[0]))); \
        v[1] = fma2_(dv[1], v[1], fma2_(th2_, bv[1], mul2_(cur2_, av[1]))); \
        M1 = M1n_; M2 = M2n_;                                               \
        if ((J) == sub) outv = MFR * thn_;                                  \
        th = thn_;                                                          \
    }

    for (int tq = 0; tq < TQ; tq += 2) {
        float outv = 0.f;
        {
            const float4 q = q0buf;
            q0buf = __ldg(cp4 + (size_t)(tq + 2) * BB);
            STEP(q.x, 0) STEP(q.y, 1) STEP(q.z, 2) STEP(q.w, 3)
            op[(size_t)tq * (4 * BB)] = outv;
        }
        {
            const float4 q = q1buf;
            q1buf = __ldg(cp4 + (size_t)(tq + 3) * BB);
            STEP(q.x, 0) STEP(q.y, 1) STEP(q.z, 2) STEP(q.w, 3)
            op[(size_t)(tq + 1) * (4 * BB)] = outv;
        }
    }
#undef STEP
}

extern "C" void kernel_launch(void* const* d_in, const int* in_sizes, int n_in,
                              void* d_out, int out_size) {
    const float* currents = (const float*)d_in[0];
    const float* a   = (const float*)d_in[1];
    const float* b   = (const float*)d_in[2];
    const float* pc  = (const float*)d_in[3];
    const float* gb  = (const float*)d_in[4];
    const float* ds  = (const float*)d_in[5];
    const float* mc  = (const float*)d_in[6];
    const float* mfr = (const float*)d_in[7];
    float* out = (float*)d_out;

    dim3 tb(32, 8), tg(TT / 32, BB / 32);
    transpose_kernel<<<tg, tb>>>(currents);
    gfr_kernel<<<(4 * BB) / 128, 128>>>(a, b, pc, gb, ds, mc, mfr, out);
}

// round 14
// speedup vs baseline: 1.1050x; 1.1050x over previous
#include <cuda_runtime.h>

#define BB 4096
#define TT 1024
#define NN 16
#define NPT 2   // packed pairs per lane: 4 lanes/row * 2 pairs * 2 = 16 filters
#define TQ (TT / 4)

// Quad-packed transposed currents: g_cur4[tq][b] = {cur[4tq..4tq+3]} for row b.
__device__ float4 g_cur4[(TQ + 4) * BB];

typedef unsigned long long u64;

__device__ __forceinline__ u64 pk2(float x, float y) {
    u64 r; asm("mov.b64 %0, {%1, %2};" : "=l"(r) : "f"(x), "f"(y)); return r;
}
__device__ __forceinline__ void upk2(u64 a, float& x, float& y) {
    asm("mov.b64 {%0, %1}, %2;" : "=f"(x), "=f"(y) : "l"(a));
}
__device__ __forceinline__ u64 fma2_(u64 a, u64 b, u64 c) {
    u64 d; asm("fma.rn.f32x2 %0, %1, %2, %3;" : "=l"(d) : "l"(a), "l"(b), "l"(c)); return d;
}
__device__ __forceinline__ u64 mul2_(u64 a, u64 b) {
    u64 d; asm("mul.rn.f32x2 %0, %1, %2;" : "=l"(d) : "l"(a), "l"(b)); return d;
}
__device__ __forceinline__ float tanh_a(float x) {
    float y; asm("tanh.approx.f32 %0, %1;" : "=f"(y) : "f"(x)); return y;
}

// ---------------------------------------------------------------------------
// Pass 1: transpose + quad-pack currents (B,T) -> g_cur4 (T/4, B) float4.
// ---------------------------------------------------------------------------
__global__ void transpose_kernel(const float* __restrict__ cur) {
    __shared__ float tile[32][33];
    const int tx = threadIdx.x, ty = threadIdx.y;
    const int t0 = blockIdx.x * 32, b0 = blockIdx.y * 32;
#pragma unroll
    for (int i = 0; i < 32; i += 8)
        tile[ty + i][tx] = cur[(size_t)(b0 + ty + i) * TT + (t0 + tx)];
    __syncthreads();
    float4 val;
    val.x = tile[tx][4 * ty + 0];
    val.y = tile[tx][4 * ty + 1];
    val.z = tile[tx][4 * ty + 2];
    val.w = tile[tx][4 * ty + 3];
    g_cur4[(size_t)((t0 >> 2) + ty) * BB + (b0 + tx)] = val;
}

// ---------------------------------------------------------------------------
// Pass 2: R9's moment-pipeline recurrence, but each thread runs TWO
// independent batch rows interleaved.
//
// WHY (calibrated from the R13 ablation): MUFU effective chain latency is
// ~50-66 cyc (EX2+RCP cost +46cyc/step over TANH), so one row's th->th chain
// is pinned at ~94 cyc regardless of arithmetic. Interleaving a second row
// fills the ~66 cyc of MUFU shadow with useful issue: per-thread issue per
// step-pair ~110-120 cyc => ~55-60 cyc per row-step (issue-bound, not
// MUFU-bound).
//
// Launch: 128 blocks x 64 threads (2 warps/block -> 2 SMSPs/SM). Each
// 4-lane group handles rows (base, base+1). All per-row structure from R9
// is kept bit-identical: 2 shfl_xor reduction with moment-pipeline slack,
// packed f32x2 filters, quad LDG, lane-owned quad STG, tanh.approx.
// ---------------------------------------------------------------------------
__global__ void __launch_bounds__(64, 1) gfr_kernel(
    const float* __restrict__ a, const float* __restrict__ b,
    const float* __restrict__ pc, const float* __restrict__ gb,
    const float* __restrict__ ds, const float* __restrict__ mc,
    const float* __restrict__ mfr, float* __restrict__ out)
{
    const int tid = threadIdx.x;
    const int sub = tid & 3;
    const int base = blockIdx.x * 32 + (tid >> 2) * 2;  // rows base, base+1
    const int f0  = sub * 4;

    const float MFR = mfr[0];
    const float invmc = 1.f / mc[0];
    const float csN = invmc * (1.f / (float)NN);

    u64 av[NPT], bv[NPT], dv[NPT], d3v[NPT];
#pragma unroll
    for (int i = 0; i < NPT; i++) {
        const float dA = 1.f - ds[f0 + 2 * i], dB = 1.f - ds[f0 + 2 * i + 1];
        av[i]  = pk2(csN * a[f0 + 2 * i], csN * a[f0 + 2 * i + 1]);
        bv[i]  = pk2(csN * 1000.f * MFR * b[f0 + 2 * i],
                     csN * 1000.f * MFR * b[f0 + 2 * i + 1]);
        dv[i]  = pk2(dA, dB);
        d3v[i] = pk2(dA * dA * dA, dB * dB * dB);
    }
    float suma = 0.f, sumb = 0.f, a1c = 0.f, b1c = 0.f, a2c = 0.f, b2c = 0.f;
#pragma unroll
    for (int n = 0; n < NN; n++) {
        const float dn = 1.f - ds[n];
        const float An = csN * a[n];
        const float Bn = csN * 1000.f * MFR * b[n];
        suma += a[n]; sumb += b[n];
        a1c += dn * An;        b1c += dn * Bn;
        a2c += dn * dn * An;   b2c += dn * dn * Bn;
    }
    const float ca = suma * csN;
    const float cb = 1000.f * MFR * sumb * csN;
    const float c0 = -gb[0] * invmc;
    const float q0 = pc[0] * pc[0], q1 = pc[1] * pc[1], q2 = pc[2] * pc[2],
                q3 = pc[3] * pc[3], q4 = pc[4] * pc[4];

    // per-row state (rows A=base, B=base+1)
    u64 vA[NPT] = {0ull, 0ull}, vB[NPT] = {0ull, 0ull};
    float thA = 0.f, M1A = 0.f, M2A = 0.f;
    float thB = 0.f, M1B = 0.f, M2B = 0.f;

    const float4* cpA = g_cur4 + base;
    const float4* cpB = g_cur4 + base + 1;
    float* opA = out + base + (size_t)sub * BB;
    float* opB = out + base + 1 + (size_t)sub * BB;

    float4 qA0 = __ldg(cpA), qA1 = __ldg(cpA + BB);
    float4 qB0 = __ldg(cpB), qB1 = __ldg(cpB + BB);

#define STEP(CUR, J, TH, M1v, M2v, V, OUTV)                                 \
    {                                                                       \
        const float cur_ = (CUR);                                           \
        const float pre_ = fmaf(cur_, ca, c0);                              \
        /* ---- th critical path ---- */                                    \
        const float x_ = fmaf(TH, cb, M1v + pre_);                          \
        const float x2_ = x_ * x_;                                          \
        const float u01_ = fmaf(q1, x_, q0);                                \
        const float u34_ = fmaf(q4, x_, q3);                                \
        const float w1s_ = fmaf(q2, x2_, u01_);                             \
        const float x3_ = x_ * x2_;                                         \
        float p_ = fmaf(u34_, x3_, w1s_);                                   \
        p_ = fmaxf(p_, 0.f);                                                \
        const float thn_ = tanh_a(p_);                                      \
        /* ---- reduction M_3[t-1] (moment-pipeline slack) ---- */          \
        u64 s_ = fma2_(d3v[1], V[1], mul2_(d3v[0], V[0]));                  \
        float sx_, sy_; upk2(s_, sx_, sy_);                                 \
        const float Wp_ = sx_ + sy_;                                        \
        const float r1_ = Wp_ + __shfl_xor_sync(0xFFFFFFFFu, Wp_, 1);       \
        const float R3_ = r1_ + __shfl_xor_sync(0xFFFFFFFFu, r1_, 2);       \
        /* ---- moment pipeline ---- */                                     \
        const float M1n_ = M2v + fmaf(TH, b1c, cur_ * a1c);                 \
        const float M2n_ = R3_ + fmaf(TH, b2c, cur_ * a2c);                 \
        /* ---- state update with OLD th ---- */                            \
        const u64 cur2_ = pk2(cur_, cur_);                                  \
        const u64 th2_  = pk2(TH, TH);                                      \
        V[0] = fma2_(dv[0], V[0], fma2_(th2_, bv[0], mul2_(cur2_, av[0]))); \
        V[1] = fma2_(dv[1], V[1], fma2_(th2_, bv[1], mul2_(cur2_, av[1]))); \
        M1v = M1n_; M2v = M2n_;                                             \
        if ((J) == sub) OUTV = thn_;                                        \
        TH = thn_;                                                          \
    }

    for (int tq = 0; tq < TQ; tq += 2) {
        {
            float ovA = 0.f, ovB = 0.f;
            const float4 qa = qA0, qb = qB0;
            qA0 = __ldg(cpA + (size_t)(tq + 2) * BB);
            qB0 = __ldg(cpB + (size_t)(tq + 2) * BB);
            STEP(qa.x, 0, thA, M1A, M2A, vA, ovA)
            STEP(qb.x, 0, thB, M1B, M2B, vB, ovB)
            STEP(qa.y, 1, thA, M1A, M2A, vA, ovA)
            STEP(qb.y, 1, thB, M1B, M2B, vB, ovB)
            STEP(qa.z, 2, thA, M1A, M2A, vA, ovA)
            STEP(qb.z, 2, thB, M1B, M2B, vB, ovB)
            STEP(qa.w, 3, thA, M1A, M2A, vA, ovA)
            STEP(qb.w, 3, thB, M1B, M2B, vB, ovB)
            opA[(size_t)tq * (4 * BB)] = MFR * ovA;
            opB[(size_t)tq * (4 * BB)] = MFR * ovB;
        }
        {
            float ovA = 0.f, ovB = 0.f;
            const float4 qa = qA1, qb = qB1;
            qA1 = __ldg(cpA + (size_t)(tq + 3) * BB);
            qB1 = __ldg(cpB + (size_t)(tq + 3) * BB);
            STEP(qa.x, 0, thA, M1A, M2A, vA, ovA)
            STEP(qb.x, 0, thB, M1B, M2B, vB, ovB)
            STEP(qa.y, 1, thA, M1A, M2A, vA, ovA)
            STEP(qb.y, 1, thB, M1B, M2B, vB, ovB)
            STEP(qa.z, 2, thA, M1A, M2A, vA, ovA)
            STEP(qb.z, 2, thB, M1B, M2B, vB, ovB)
            STEP(qa.w, 3, thA, M1A, M2A, vA, ovA)
            STEP(qb.w, 3, thB, M1B, M2B, vB, ovB)
            opA[(size_t)(tq + 1) * (4 * BB)] = MFR * ovA;
            opB[(size_t)(tq + 1) * (4 * BB)] = MFR * ovB;
        }
    }
#undef STEP
}

extern "C" void kernel_launch(void* const* d_in, const int* in_sizes, int n_in,
                              void* d_out, int out_size) {
    const float* currents = (const float*)d_in[0];
    const float* a   = (const float*)d_in[1];
    const float* b   = (const float*)d_in[2];
    const float* pc  = (const float*)d_in[3];
    const float* gb  = (const float*)d_in[4];
    const float* ds  = (const float*)d_in[5];
    const float* mc  = (const float*)d_in[6];
    const float* mfr = (const float*)d_in[7];
    float* out = (float*)d_out;

    dim3 tb(32, 8), tg(TT / 32, BB / 32);
    transpose_kernel<<<tg, tb>>>(currents);
    // 4 lanes/row, 2 rows/thread: 8192 threads = 128 blocks x 64
    gfr_kernel<<<128, 64>>>(a, b, pc, gb, ds, mc, mfr, out);
}

// round 15
// speedup vs baseline: 1.6565x; 1.4991x over previous
#include <cuda_runtime.h>

#define BB 4096
#define TT 1024
#define NN 16
#define NPT 2   // packed pairs per lane: 4 lanes/row * 2 pairs * 2 = 16 filters
#define TQ (TT / 4)

// Quad-packed transposed currents: g_cur4[tq][b] = {cur[4tq..4tq+3]} for row b.
__device__ float4 g_cur4[(TQ + 4) * BB];

typedef unsigned long long u64;

__device__ __forceinline__ u64 pk2(float x, float y) {
    u64 r; asm("mov.b64 %0, {%1, %2};" : "=l"(r) : "f"(x), "f"(y)); return r;
}
__device__ __forceinline__ void upk2(u64 a, float& x, float& y) {
    asm("mov.b64 {%0, %1}, %2;" : "=f"(x), "=f"(y) : "l"(a));
}
__device__ __forceinline__ u64 fma2_(u64 a, u64 b, u64 c) {
    u64 d; asm("fma.rn.f32x2 %0, %1, %2, %3;" : "=l"(d) : "l"(a), "l"(b), "l"(c)); return d;
}
__device__ __forceinline__ u64 mul2_(u64 a, u64 b) {
    u64 d; asm("mul.rn.f32x2 %0, %1, %2;" : "=l"(d) : "l"(a), "l"(b)); return d;
}
__device__ __forceinline__ float tanh_a(float x) {
    float y; asm("tanh.approx.f32 %0, %1;" : "=f"(y) : "f"(x)); return y;
}

// ---------------------------------------------------------------------------
// Pass 1: transpose + quad-pack currents (B,T) -> g_cur4 (T/4, B) float4.
// ---------------------------------------------------------------------------
__global__ void transpose_kernel(const float* __restrict__ cur) {
    __shared__ float tile[32][33];
    const int tx = threadIdx.x, ty = threadIdx.y;
    const int t0 = blockIdx.x * 32, b0 = blockIdx.y * 32;
#pragma unroll
    for (int i = 0; i < 32; i += 8)
        tile[ty + i][tx] = cur[(size_t)(b0 + ty + i) * TT + (t0 + tx)];
    __syncthreads();
    float4 val;
    val.x = tile[tx][4 * ty + 0];
    val.y = tile[tx][4 * ty + 1];
    val.z = tile[tx][4 * ty + 2];
    val.w = tile[tx][4 * ty + 3];
    g_cur4[(size_t)((t0 >> 2) + ty) * BB + (b0 + tx)] = val;
}

// ---------------------------------------------------------------------------
// Pass 2: R9 structure (best: 53.3us = 94 cyc/step) with the serial chain
// shaved.
//
// Calibrated model (R13 ablation): chained MUFU = ~38 cyc; R9 chain =
// x(4) + Estrin(16) + max(4) + tanh(38) = 62, plus ~32 cyc in-order-issue
// residual = 94. Changes:
//  1. depth-12 / 5-op Estrin:  p = fma(fma(q4,x2,t2), x2, t1),
//     t1 = fma(q1,x,q0), t2 = fma(q3,x,q2), x2 = x*x.
//     (one fewer instr AND -4 cyc depth vs the old 6-op/16-deep form)
//  2. the 4 per-quad `pre = fma(cur, ca, c0)` are computed at quad-load
//     time so the in-order window around the tanh consumer carries only
//     reduction/moment/state work.
// Wall time = 1024 * T_step (every row ticks in parallel; interleaving
// more rows per thread only lengthens the serial program — R14 lesson).
// ---------------------------------------------------------------------------
__global__ void __launch_bounds__(128, 1) gfr_kernel(
    const float* __restrict__ a, const float* __restrict__ b,
    const float* __restrict__ pc, const float* __restrict__ gb,
    const float* __restrict__ ds, const float* __restrict__ mc,
    const float* __restrict__ mfr, float* __restrict__ out)
{
    const int tid = threadIdx.x;
    const int sub = tid & 3;
    const int row = blockIdx.x * 32 + (tid >> 2);
    const int f0  = sub * 4;

    const float MFR = mfr[0];
    const float invmc = 1.f / mc[0];
    const float csN = invmc * (1.f / (float)NN);

    u64 av[NPT], bv[NPT], dv[NPT], d3v[NPT], v[NPT];
#pragma unroll
    for (int i = 0; i < NPT; i++) {
        const float dA = 1.f - ds[f0 + 2 * i], dB = 1.f - ds[f0 + 2 * i + 1];
        av[i]  = pk2(csN * a[f0 + 2 * i], csN * a[f0 + 2 * i + 1]);
        bv[i]  = pk2(csN * 1000.f * MFR * b[f0 + 2 * i],
                     csN * 1000.f * MFR * b[f0 + 2 * i + 1]);
        dv[i]  = pk2(dA, dB);
        d3v[i] = pk2(dA * dA * dA, dB * dB * dB);
        v[i] = 0ull;
    }
    float suma = 0.f, sumb = 0.f, a1c = 0.f, b1c = 0.f, a2c = 0.f, b2c = 0.f;
#pragma unroll
    for (int n = 0; n < NN; n++) {
        const float dn = 1.f - ds[n];
        const float An = csN * a[n];
        const float Bn = csN * 1000.f * MFR * b[n];
        suma += a[n]; sumb += b[n];
        a1c += dn * An;        b1c += dn * Bn;
        a2c += dn * dn * An;   b2c += dn * dn * Bn;
    }
    const float ca = suma * csN;
    const float cb = 1000.f * MFR * sumb * csN;
    const float c0 = -gb[0] * invmc;
    const float q0 = pc[0] * pc[0], q1 = pc[1] * pc[1], q2 = pc[2] * pc[2],
                q3 = pc[3] * pc[3], q4 = pc[4] * pc[4];

    const float4* cp4 = g_cur4 + row;
    float* op = out + row + (size_t)sub * BB;
    float th = 0.f, M1 = 0.f, M2 = 0.f;

    float4 q0buf = __ldg(cp4);
    float4 q1buf = __ldg(cp4 + BB);

#define STEP(CUR, PRE, J)                                                   \
    {                                                                       \
        const float cur_ = (CUR);                                           \
        /* ---- th critical path: x -> depth-12 Estrin -> max -> tanh ---- */\
        const float x_ = fmaf(th, cb, M1 + (PRE));                          \
        const float t1_ = fmaf(q1, x_, q0);                                 \
        const float t2_ = fmaf(q3, x_, q2);                                 \
        const float x2_ = x_ * x_;                                          \
        float p_ = fmaf(fmaf(q4, x2_, t2_), x2_, t1_);                      \
        p_ = fmaxf(p_, 0.f);                                                \
        const float thn_ = tanh_a(p_);                                      \
        /* ---- reduction M_3[t-1] (moment-pipeline slack) ---- */          \
        u64 s_ = fma2_(d3v[1], v[1], mul2_(d3v[0], v[0]));                  \
        float sx_, sy_; upk2(s_, sx_, sy_);                                 \
        const float Wp_ = sx_ + sy_;                                        \
        const float r1_ = Wp_ + __shfl_xor_sync(0xFFFFFFFFu, Wp_, 1);       \
        const float R3_ = r1_ + __shfl_xor_sync(0xFFFFFFFFu, r1_, 2);       \
        /* ---- moment pipeline ---- */                                     \
        const float M1n_ = M2 + fmaf(th, b1c, cur_ * a1c);                  \
        const float M2n_ = R3_ + fmaf(th, b2c, cur_ * a2c);                 \
        /* ---- state update with OLD th ---- */                            \
        const u64 cur2_ = pk2(cur_, cur_);                                  \
        const u64 th2_  = pk2(th, th);                                      \
        v[0] = fma2_(dv[0], v[0], fma2_(th2_, bv[0], mul2_(cur2_, av[0]))); \
        v[1] = fma2_(dv[1], v[1], fma2_(th2_, bv[1], mul2_(cur2_, av[1]))); \
        M1 = M1n_; M2 = M2n_;                                               \
        if ((J) == sub) outv = thn_;                                        \
        th = thn_;                                                          \
    }

    for (int tq = 0; tq < TQ; tq += 2) {
        {
            float outv = 0.f;
            const float4 q = q0buf;
            q0buf = __ldg(cp4 + (size_t)(tq + 2) * BB);
            // batch the 4 pre-FMAs at quad boundaries (off the chain window)
            const float pr0 = fmaf(q.x, ca, c0), pr1 = fmaf(q.y, ca, c0);
            const float pr2 = fmaf(q.z, ca, c0), pr3 = fmaf(q.w, ca, c0);
            STEP(q.x, pr0, 0) STEP(q.y, pr1, 1) STEP(q.z, pr2, 2) STEP(q.w, pr3, 3)
            op[(size_t)tq * (4 * BB)] = MFR * outv;
        }
        {
            float outv = 0.f;
            const float4 q = q1buf;
            q1buf = __ldg(cp4 + (size_t)(tq + 3) * BB);
            const float pr0 = fmaf(q.x, ca, c0), pr1 = fmaf(q.y, ca, c0);
            const float pr2 = fmaf(q.z, ca, c0), pr3 = fmaf(q.w, ca, c0);
            STEP(q.x, pr0, 0) STEP(q.y, pr1, 1) STEP(q.z, pr2, 2) STEP(q.w, pr3, 3)
            op[(size_t)(tq + 1) * (4 * BB)] = MFR * outv;
        }
    }
#undef STEP
}

extern "C" void kernel_launch(void* const* d_in, const int* in_sizes, int n_in,
                              void* d_out, int out_size) {
    const float* currents = (const float*)d_in[0];
    const float* a   = (const float*)d_in[1];
    const float* b   = (const float*)d_in[2];
    const float* pc  = (const float*)d_in[3];
    const float* gb  = (const float*)d_in[4];
    const float* ds  = (const float*)d_in[5];
    const float* mc  = (const float*)d_in[6];
    const float* mfr = (const float*)d_in[7];
    float* out = (float*)d_out;

    dim3 tb(32, 8), tg(TT / 32, BB / 32);
    transpose_kernel<<<tg, tb>>>(currents);
    gfr_kernel<<<(4 * BB) / 128, 128>>>(a, b, pc, gb, ds, mc, mfr, out);
}